// round 13
// baseline (speedup 1.0000x reference)
#include <cuda_runtime.h>
#include <cuda_bf16.h>
#include <math.h>
#include <stdint.h>

#define N_NODES 50000
#define N_EDGES 800000
#define N_GRAPHS 64
#define HEADS 4
#define IN_CH 128
#define HID_CH 64
#define OUT_CH 32
#define CH1 (HEADS*HID_CH)   // 256
#define CH2 (HEADS*OUT_CH)   // 128

#define SCAN_B 1024
#define NB ((N_NODES + SCAN_B - 1) / SCAN_B)   // 49

// ---------------- scratch (device globals) ----------------------------------
// INVARIANT: g_cnt, g_lsum, g_counts are all-zero at kernel_launch entry.
__device__ __nv_bfloat162 g_h1b[N_NODES * CH1 / 2];
__device__ __nv_bfloat162 g_h1gatb[N_NODES * CH1 / 2];
__device__ __nv_bfloat162 g_h2b[N_NODES * CH2 / 2];
__device__ float g_s1[N_NODES * HEADS], g_d1[N_NODES * HEADS];
__device__ float g_s2[N_NODES * HEADS], g_d2[N_NODES * HEADS];
__device__ int   g_cnt[N_NODES];
__device__ int   g_incl[N_NODES];
__device__ int   g_indptr[N_NODES + 1];
__device__ int   g_esrc[N_EDGES];
__device__ int   g_blocksums[NB];
__device__ float g_lsum[N_GRAPHS * 2];
__device__ int   g_counts[N_GRAPHS];

__device__ __forceinline__ float lrelu(float x) {
    return x > 0.f ? x : 0.2f * x;
}

// ---------------- CSR build --------------------------------------------------
__global__ void count_kernel(const int* __restrict__ ei) {
    int e = blockIdx.x * blockDim.x + threadIdx.x;
    if (e < N_EDGES) atomicAdd(&g_cnt[ei[N_EDGES + e]], 1);
}

__global__ void scan1_kernel() {
    __shared__ int sh[SCAN_B];
    int i = blockIdx.x * SCAN_B + threadIdx.x;
    int v = (i < N_NODES) ? g_cnt[i] : 0;
    sh[threadIdx.x] = v;
    __syncthreads();
    #pragma unroll
    for (int off = 1; off < SCAN_B; off <<= 1) {
        int t = (threadIdx.x >= off) ? sh[threadIdx.x - off] : 0;
        __syncthreads();
        sh[threadIdx.x] += t;
        __syncthreads();
    }
    if (i < N_NODES) g_incl[i] = sh[threadIdx.x];
    if (threadIdx.x == SCAN_B - 1) g_blocksums[blockIdx.x] = sh[SCAN_B - 1];
}

__global__ void scan2_kernel() {
    __shared__ int sh[64];
    int t = threadIdx.x;
    int v = (t < NB) ? g_blocksums[t] : 0;
    sh[t] = v;
    __syncthreads();
    #pragma unroll
    for (int off = 1; off < 64; off <<= 1) {
        int u = (t >= off) ? sh[t - off] : 0;
        __syncthreads();
        sh[t] += u;
        __syncthreads();
    }
    if (t < NB) g_blocksums[t] = sh[t] - v;   // exclusive
}

__global__ void scan3_kernel() {
    int i = blockIdx.x * blockDim.x + threadIdx.x;
    if (i < N_NODES) g_indptr[i + 1] = g_incl[i] + g_blocksums[i / SCAN_B];
    if (i == 0) g_indptr[0] = 0;
}

// scatter: atomicSub on g_cnt restores it to 0 (keeps the zero-invariant)
__global__ void scatter_kernel(const int* __restrict__ ei) {
    int e = blockIdx.x * blockDim.x + threadIdx.x;
    if (e < N_EDGES) {
        int s = ei[e];
        int d = ei[N_EDGES + e];
        int pos = g_indptr[d] + atomicSub(&g_cnt[d], 1) - 1;
        g_esrc[pos] = s;
    }
}

// ---------------- tf32 tensor-core GEMM + fused s,d epilogue ------------------
#define BM 128
#define BN 64
#define BK 32
#define ASTRIDE 36
#define BSTRIDE 72

__device__ __forceinline__ float cvt_tf32(float x) {
    uint32_t r;
    asm("cvt.rna.tf32.f32 %0, %1;" : "=r"(r) : "f"(x));
    return __uint_as_float(r);
}

__device__ __forceinline__ void mma_tf32(float c[4], const float a[4], const float b[2]) {
    asm volatile(
        "mma.sync.aligned.m16n8k8.row.col.f32.tf32.tf32.f32 "
        "{%0,%1,%2,%3}, {%4,%5,%6,%7}, {%8,%9}, {%0,%1,%2,%3};"
        : "+f"(c[0]), "+f"(c[1]), "+f"(c[2]), "+f"(c[3])
        : "r"(__float_as_uint(a[0])), "r"(__float_as_uint(a[1])),
          "r"(__float_as_uint(a[2])), "r"(__float_as_uint(a[3])),
          "r"(__float_as_uint(b[0])), "r"(__float_as_uint(b[1])));
}

template <int LAYER>
__global__ __launch_bounds__(256) void gemm_tf32_kernel(
    const float* __restrict__ Ain, const float* __restrict__ B,
    const float* __restrict__ a_src, const float* __restrict__ a_dst)
{
    constexpr int N = (LAYER == 1) ? CH1 : CH2;
    constexpr int K = (LAYER == 1) ? IN_CH : CH1;
    const int M = N_NODES;
    __nv_bfloat162* Cb = (LAYER == 1) ? g_h1b : g_h2b;
    float* gs = (LAYER == 1) ? g_s1 : g_s2;
    float* gd = (LAYER == 1) ? g_d1 : g_d2;

    __shared__ float As[BM][ASTRIDE];
    __shared__ float Bs[BK][BSTRIDE];

    int tid = threadIdx.x;
    int brow = blockIdx.y * BM;
    int bcol = blockIdx.x * BN;
    int wid = tid >> 5, lane = tid & 31;
    int wm = wid & 3, wn = wid >> 2;
    int grp = lane >> 2;
    int q = lane & 3;

    int ar = tid >> 3;
    int ac4 = (tid & 7) << 2;
    int ar2 = tid >> 2;
    int ac8 = (tid & 3) << 3;
    int bc4 = (tid & 15) << 2;
    int br0 = tid >> 4;

    float4 ra[4];
    uint4  rab[2];
    float4 rb[2];

    auto load_regs = [&](int k0) {
        if (LAYER == 1) {
            #pragma unroll
            for (int i = 0; i < 4; i++) {
                int gr = brow + ar + i * 32;
                ra[i] = make_float4(0.f, 0.f, 0.f, 0.f);
                if (gr < M) ra[i] = *(const float4*)&Ain[(size_t)gr * K + k0 + ac4];
            }
        } else {
            #pragma unroll
            for (int i = 0; i < 2; i++) {
                int gr = brow + ar2 + i * 64;
                rab[i] = make_uint4(0, 0, 0, 0);
                if (gr < M)
                    rab[i] = *(const uint4*)&g_h1gatb[((size_t)gr * K + k0 + ac8) >> 1];
            }
        }
        #pragma unroll
        for (int i = 0; i < 2; i++) {
            int r = br0 + i * 16;
            rb[i] = *(const float4*)&B[(size_t)(k0 + r) * N + bcol + bc4];
        }
    };
    auto store_smem = [&]() {
        if (LAYER == 1) {
            #pragma unroll
            for (int i = 0; i < 4; i++) {
                int r = ar + i * 32;
                As[r][ac4 + 0] = cvt_tf32(ra[i].x);
                As[r][ac4 + 1] = cvt_tf32(ra[i].y);
                As[r][ac4 + 2] = cvt_tf32(ra[i].z);
                As[r][ac4 + 3] = cvt_tf32(ra[i].w);
            }
        } else {
            #pragma unroll
            for (int i = 0; i < 2; i++) {
                int r = ar2 + i * 64;
                const __nv_bfloat162* p = (const __nv_bfloat162*)&rab[i];
                #pragma unroll
                for (int j = 0; j < 4; j++) {
                    float2 f = __bfloat1622float2(p[j]);
                    As[r][ac8 + j * 2 + 0] = f.x;
                    As[r][ac8 + j * 2 + 1] = f.y;
                }
            }
        }
        #pragma unroll
        for (int i = 0; i < 2; i++) {
            int r = br0 + i * 16;
            Bs[r][bc4 + 0] = cvt_tf32(rb[i].x);
            Bs[r][bc4 + 1] = cvt_tf32(rb[i].y);
            Bs[r][bc4 + 2] = cvt_tf32(rb[i].z);
            Bs[r][bc4 + 3] = cvt_tf32(rb[i].w);
        }
    };

    float c[2][4][4];
    #pragma unroll
    for (int mt = 0; mt < 2; mt++)
        #pragma unroll
        for (int nt = 0; nt < 4; nt++)
            #pragma unroll
            for (int r = 0; r < 4; r++) c[mt][nt][r] = 0.f;

    load_regs(0);
    store_smem();
    __syncthreads();

    for (int k0 = 0; k0 < K; k0 += BK) {
        bool has_next = (k0 + BK) < K;
        if (has_next) load_regs(k0 + BK);

        #pragma unroll
        for (int ks = 0; ks < BK / 8; ks++) {
            int kk = ks * 8;
            float a[2][4], b[4][2];
            #pragma unroll
            for (int mt = 0; mt < 2; mt++) {
                int mb = wm * 32 + mt * 16 + grp;
                a[mt][0] = As[mb][kk + q];
                a[mt][1] = As[mb + 8][kk + q];
                a[mt][2] = As[mb][kk + q + 4];
                a[mt][3] = As[mb + 8][kk + q + 4];
            }
            #pragma unroll
            for (int nt = 0; nt < 4; nt++) {
                int nb = wn * 32 + nt * 8 + grp;
                b[nt][0] = Bs[kk + q][nb];
                b[nt][1] = Bs[kk + q + 4][nb];
            }
            #pragma unroll
            for (int mt = 0; mt < 2; mt++)
                #pragma unroll
                for (int nt = 0; nt < 4; nt++)
                    mma_tf32(c[mt][nt], a[mt], b[nt]);
        }
        __syncthreads();
        if (has_next) {
            store_smem();
            __syncthreads();
        }
    }

    // ---- epilogue 1: pack fp32 -> bf162 store of h ----
    #pragma unroll
    for (int mt = 0; mt < 2; mt++) {
        int rg0 = brow + wm * 32 + mt * 16 + grp;
        #pragma unroll
        for (int nt = 0; nt < 4; nt++) {
            int cg = bcol + wn * 32 + nt * 8 + q * 2;
            if (rg0 < M)
                Cb[((size_t)rg0 * N + cg) >> 1] =
                    __floats2bfloat162_rn(c[mt][nt][0], c[mt][nt][1]);
            if (rg0 + 8 < M)
                Cb[((size_t)(rg0 + 8) * N + cg) >> 1] =
                    __floats2bfloat162_rn(c[mt][nt][2], c[mt][nt][3]);
        }
    }

    // ---- epilogue 2: fused s,d per (row, head) ----
    constexpr int HC = (LAYER == 1) ? HID_CH : OUT_CH;
    float ps[2][2] = {{0.f, 0.f}, {0.f, 0.f}};
    float pd[2][2] = {{0.f, 0.f}, {0.f, 0.f}};
    {
        int hh = (LAYER == 1) ? (bcol / HID_CH) : (bcol / OUT_CH + wn);
        #pragma unroll
        for (int nt = 0; nt < 4; nt++) {
            int ch = (LAYER == 1) ? (wn * 32 + nt * 8 + q * 2) : (nt * 8 + q * 2);
            float a0 = a_src[hh * HC + ch], a1 = a_src[hh * HC + ch + 1];
            float d0 = a_dst[hh * HC + ch], d1 = a_dst[hh * HC + ch + 1];
            #pragma unroll
            for (int mt = 0; mt < 2; mt++) {
                ps[mt][0] += c[mt][nt][0] * a0 + c[mt][nt][1] * a1;
                pd[mt][0] += c[mt][nt][0] * d0 + c[mt][nt][1] * d1;
                ps[mt][1] += c[mt][nt][2] * a0 + c[mt][nt][3] * a1;
                pd[mt][1] += c[mt][nt][2] * d0 + c[mt][nt][3] * d1;
            }
        }
        #pragma unroll
        for (int mt = 0; mt < 2; mt++)
            #pragma unroll
            for (int hf = 0; hf < 2; hf++) {
                ps[mt][hf] += __shfl_down_sync(0xffffffff, ps[mt][hf], 2);
                ps[mt][hf] += __shfl_down_sync(0xffffffff, ps[mt][hf], 1);
                pd[mt][hf] += __shfl_down_sync(0xffffffff, pd[mt][hf], 2);
                pd[mt][hf] += __shfl_down_sync(0xffffffff, pd[mt][hf], 1);
            }

        if (LAYER == 2) {
            if (q == 0) {
                #pragma unroll
                for (int mt = 0; mt < 2; mt++)
                    #pragma unroll
                    for (int hf = 0; hf < 2; hf++) {
                        int grow = brow + wm * 32 + mt * 16 + grp + hf * 8;
                        if (grow < M) {
                            gs[grow * HEADS + hh] = ps[mt][hf];
                            gd[grow * HEADS + hh] = pd[mt][hf];
                        }
                    }
            }
        } else {
            float* red = &As[0][0];
            if (q == 0) {
                #pragma unroll
                for (int mt = 0; mt < 2; mt++)
                    #pragma unroll
                    for (int hf = 0; hf < 2; hf++) {
                        int row = wm * 32 + mt * 16 + grp + hf * 8;
                        red[wn * 256 + row * 2 + 0] = ps[mt][hf];
                        red[wn * 256 + row * 2 + 1] = pd[mt][hf];
                    }
            }
            __syncthreads();
            if (tid < 128) {
                int grow = brow + tid;
                if (grow < M) {
                    float sv = red[tid * 2]     + red[256 + tid * 2];
                    float dv = red[tid * 2 + 1] + red[256 + tid * 2 + 1];
                    gs[grow * HEADS + hh] = sv;
                    gd[grow * HEADS + hh] = dv;
                }
            }
        }
    }
}

// ---------------- warp-per-node GAT softmax-aggregate (vectorized) ------------
// One warp per node. Lane owns CONTIGUOUS channel-pairs:
//   L1: pairs [4*lane, 4*lane+4) -> one uint4 (16 B) load per gathered row
//   L2: pairs [2*lane, 2*lane+2) -> one uint2 (8 B) load per gathered row
// Contiguity => each lane belongs to exactly one head: hh = lane >> 3.
// LAYER==2 fuses bias+relu+Wout projection + pooled logit atomics.
template <int LAYER>
__global__ __launch_bounds__(256) void agg_kernel(const float* __restrict__ bias,
                                                  const int* __restrict__ batch,
                                                  const float* __restrict__ Wout)
{
    constexpr int CH = (LAYER == 1) ? CH1 : CH2;
    constexpr int PAIRS = CH / 2;             // 128 / 64
    constexpr int PPL = PAIRS / 32;           // 4 / 2 pairs per lane

    int n = blockIdx.x * (blockDim.x >> 5) + (threadIdx.x >> 5);
    if (n >= N_NODES) return;
    int lane = threadIdx.x & 31;
    int hh = lane >> 3;                       // head of this lane (both layers)
    int p0 = lane * PPL;                      // first owned pair

    const __nv_bfloat162* hb = (LAYER == 1) ? g_h1b : g_h2b;
    const float* s = (LAYER == 1) ? g_s1 : g_s2;
    const float* d = (LAYER == 1) ? g_d1 : g_d2;

    float4 dn4 = *(const float4*)&d[n * 4];
    float4 ss4 = *(const float4*)&s[n * 4];

    float wself4[HEADS];
    wself4[0] = __expf(lrelu(ss4.x + dn4.x));
    wself4[1] = __expf(lrelu(ss4.y + dn4.y));
    wself4[2] = __expf(lrelu(ss4.z + dn4.z));
    wself4[3] = __expf(lrelu(ss4.w + dn4.w));
    float wself = wself4[hh];
    float denom = wself;

    float acc[PPL][2];
    {
        __nv_bfloat162 hv[PPL];
        if (LAYER == 1) *(uint4*)hv = *(const uint4*)&hb[(size_t)n * PAIRS + p0];
        else            *(uint2*)hv = *(const uint2*)&hb[(size_t)n * PAIRS + p0];
        #pragma unroll
        for (int i = 0; i < PPL; i++) {
            float2 f = __bfloat1622float2(hv[i]);
            acc[i][0] = wself * f.x;
            acc[i][1] = wself * f.y;
        }
    }

    int beg = g_indptr[n], end = g_indptr[n + 1];
    for (int base = beg; base < end; base += 32) {
        int m = min(32, end - base);
        int srcl = 0;
        float4 wl = make_float4(0.f, 0.f, 0.f, 0.f);
        if (lane < m) {
            srcl = g_esrc[base + lane];
            float4 s4 = *(const float4*)&s[srcl * 4];
            wl.x = __expf(lrelu(s4.x + dn4.x));
            wl.y = __expf(lrelu(s4.y + dn4.y));
            wl.z = __expf(lrelu(s4.z + dn4.z));
            wl.w = __expf(lrelu(s4.w + dn4.w));
        }
        #pragma unroll 4
        for (int j = 0; j < m; j++) {
            int src = __shfl_sync(0xffffffffu, srcl, j);
            float w0 = __shfl_sync(0xffffffffu, wl.x, j);
            float w1 = __shfl_sync(0xffffffffu, wl.y, j);
            float w2 = __shfl_sync(0xffffffffu, wl.z, j);
            float w3 = __shfl_sync(0xffffffffu, wl.w, j);
            float w = (hh == 0) ? w0 : (hh == 1) ? w1 : (hh == 2) ? w2 : w3;
            __nv_bfloat162 hv[PPL];
            if (LAYER == 1) *(uint4*)hv = *(const uint4*)&hb[(size_t)src * PAIRS + p0];
            else            *(uint2*)hv = *(const uint2*)&hb[(size_t)src * PAIRS + p0];
            #pragma unroll
            for (int i = 0; i < PPL; i++) {
                float2 f = __bfloat1622float2(hv[i]);
                acc[i][0] += w * f.x;
                acc[i][1] += w * f.y;
            }
            denom += w;
        }
    }

    float inv = 1.f / (denom + 1e-16f);

    if (LAYER == 1) {
        __nv_bfloat162 ov[PPL];
        #pragma unroll
        for (int i = 0; i < PPL; i++) {
            int p = p0 + i;
            float2 bi = *(const float2*)&bias[2 * p];
            float v0 = fmaxf(acc[i][0] * inv + bi.x, 0.f);
            float v1 = fmaxf(acc[i][1] * inv + bi.y, 0.f);
            ov[i] = __floats2bfloat162_rn(v0, v1);
        }
        *(uint4*)&g_h1gatb[(size_t)n * PAIRS + p0] = *(uint4*)ov;
    } else {
        float l0 = 0.f, l1 = 0.f;
        #pragma unroll
        for (int i = 0; i < PPL; i++) {
            int p = p0 + i;
            float2 bi = *(const float2*)&bias[2 * p];
            float v0 = fmaxf(acc[i][0] * inv + bi.x, 0.f);
            float v1 = fmaxf(acc[i][1] * inv + bi.y, 0.f);
            float4 w = *(const float4*)&Wout[4 * p];
            l0 += v0 * w.x + v1 * w.z;
            l1 += v0 * w.y + v1 * w.w;
        }
        #pragma unroll
        for (int off = 16; off > 0; off >>= 1) {
            l0 += __shfl_down_sync(0xffffffffu, l0, off);
            l1 += __shfl_down_sync(0xffffffffu, l1, off);
        }
        if (lane == 0) {
            int gb = batch[n];
            atomicAdd(&g_lsum[gb * 2 + 0], l0);
            atomicAdd(&g_lsum[gb * 2 + 1], l1);
            atomicAdd(&g_counts[gb], 1);
        }
    }
}

// ---------------- final logits + softmax (+ scratch re-zero) ------------------
__global__ void final_kernel(const float* __restrict__ bout,
                             float* __restrict__ out)
{
    int g = threadIdx.x;
    if (g >= N_GRAPHS) return;
    float cnt = fmaxf((float)g_counts[g], 1.0f);
    float l0 = g_lsum[g * 2 + 0] / cnt + bout[0];
    float l1 = g_lsum[g * 2 + 1] / cnt + bout[1];
    float mx = fmaxf(l0, l1);
    float e0 = expf(l0 - mx), e1 = expf(l1 - mx);
    float inv = 1.f / (e0 + e1);
    out[g * 2 + 0] = e0 * inv;
    out[g * 2 + 1] = e1 * inv;
    g_lsum[g * 2 + 0] = 0.f;
    g_lsum[g * 2 + 1] = 0.f;
    g_counts[g] = 0;
}

// ---------------- launch -------------------------------------------------------
extern "C" void kernel_launch(void* const* d_in, const int* in_sizes, int n_in,
                              void* d_out, int out_size) {
    const float* x      = (const float*)d_in[0];
    const int*   ei     = (const int*)d_in[1];
    const int*   batch  = (const int*)d_in[2];
    const float* W1     = (const float*)d_in[3];
    const float* a_src1 = (const float*)d_in[4];
    const float* a_dst1 = (const float*)d_in[5];
    const float* b1     = (const float*)d_in[6];
    const float* W2     = (const float*)d_in[7];
    const float* a_src2 = (const float*)d_in[8];
    const float* a_dst2 = (const float*)d_in[9];
    const float* b2     = (const float*)d_in[10];
    const float* Wout   = (const float*)d_in[11];
    const float* bout   = (const float*)d_in[12];
    float* out = (float*)d_out;

    count_kernel<<<(N_EDGES + 255) / 256, 256>>>(ei);
    scan1_kernel<<<NB, SCAN_B>>>();
    scan2_kernel<<<1, 64>>>();
    scan3_kernel<<<(N_NODES + 255) / 256, 256>>>();
    scatter_kernel<<<(N_EDGES + 255) / 256, 256>>>(ei);

    {
        dim3 grid(CH1 / BN, (N_NODES + BM - 1) / BM);
        gemm_tf32_kernel<1><<<grid, 256>>>(x, W1, a_src1, a_dst1);
    }
    agg_kernel<1><<<(N_NODES * 32 + 255) / 256, 256>>>(b1, batch, Wout);

    {
        dim3 grid(CH2 / BN, (N_NODES + BM - 1) / BM);
        gemm_tf32_kernel<2><<<grid, 256>>>(nullptr, W2, a_src2, a_dst2);
    }
    agg_kernel<2><<<(N_NODES * 32 + 255) / 256, 256>>>(b2, batch, Wout);

    final_kernel<<<1, 64>>>(bout, out);
}

// round 14
// speedup vs baseline: 1.0226x; 1.0226x over previous
#include <cuda_runtime.h>
#include <cuda_bf16.h>
#include <math.h>
#include <stdint.h>

#define N_NODES 50000
#define N_EDGES 800000
#define N_GRAPHS 64
#define HEADS 4
#define IN_CH 128
#define HID_CH 64
#define OUT_CH 32
#define CH1 (HEADS*HID_CH)   // 256
#define CH2 (HEADS*OUT_CH)   // 128

#define SCAN_B 1024
#define NB ((N_NODES + SCAN_B - 1) / SCAN_B)   // 49

// ---------------- scratch (device globals) ----------------------------------
// INVARIANT: g_cnt, g_lsum, g_counts are all-zero at kernel_launch entry.
__device__ __nv_bfloat162 g_h1b[N_NODES * CH1 / 2];
__device__ __nv_bfloat162 g_h1gatb[N_NODES * CH1 / 2];
__device__ __nv_bfloat162 g_h2b[N_NODES * CH2 / 2];
__device__ float g_s1[N_NODES * HEADS], g_d1[N_NODES * HEADS];
__device__ float g_s2[N_NODES * HEADS], g_d2[N_NODES * HEADS];
__device__ int   g_cnt[N_NODES];
__device__ int   g_incl[N_NODES];
__device__ int   g_indptr[N_NODES + 1];
__device__ int   g_esrc[N_EDGES];
__device__ int   g_blocksums[NB];
__device__ float g_lsum[N_GRAPHS * 2];
__device__ int   g_counts[N_GRAPHS];

__device__ __forceinline__ float lrelu(float x) {
    return x > 0.f ? x : 0.2f * x;
}

// ---------------- CSR build --------------------------------------------------
__global__ void count_kernel(const int* __restrict__ ei) {
    int e = blockIdx.x * blockDim.x + threadIdx.x;
    if (e < N_EDGES) atomicAdd(&g_cnt[ei[N_EDGES + e]], 1);
}

__global__ void scan1_kernel() {
    __shared__ int sh[SCAN_B];
    int i = blockIdx.x * SCAN_B + threadIdx.x;
    int v = (i < N_NODES) ? g_cnt[i] : 0;
    sh[threadIdx.x] = v;
    __syncthreads();
    #pragma unroll
    for (int off = 1; off < SCAN_B; off <<= 1) {
        int t = (threadIdx.x >= off) ? sh[threadIdx.x - off] : 0;
        __syncthreads();
        sh[threadIdx.x] += t;
        __syncthreads();
    }
    if (i < N_NODES) g_incl[i] = sh[threadIdx.x];
    if (threadIdx.x == SCAN_B - 1) g_blocksums[blockIdx.x] = sh[SCAN_B - 1];
}

// fused scan2+scan3: every block re-scans the NB block sums in smem (cheap),
// then applies the exclusive block prefix. g_blocksums is left UNMODIFIED.
__global__ void scan23_kernel() {
    __shared__ int incl[64];
    __shared__ int excl[64];
    int t = threadIdx.x;
    int own = 0;
    if (t < 64) {
        own = (t < NB) ? g_blocksums[t] : 0;
        incl[t] = own;
    }
    __syncthreads();
    #pragma unroll
    for (int off = 1; off < 64; off <<= 1) {
        int u = (t >= off && t < 64) ? incl[t - off] : 0;
        __syncthreads();
        if (t < 64) incl[t] += u;
        __syncthreads();
    }
    if (t < 64) excl[t] = incl[t] - own;
    __syncthreads();
    int i = blockIdx.x * blockDim.x + t;
    if (i < N_NODES) g_indptr[i + 1] = g_incl[i] + excl[i / SCAN_B];
    if (i == 0) g_indptr[0] = 0;
}

// scatter: atomicSub on g_cnt restores it to 0 (keeps the zero-invariant)
__global__ void scatter_kernel(const int* __restrict__ ei) {
    int e = blockIdx.x * blockDim.x + threadIdx.x;
    if (e < N_EDGES) {
        int s = ei[e];
        int d = ei[N_EDGES + e];
        int pos = g_indptr[d] + atomicSub(&g_cnt[d], 1) - 1;
        g_esrc[pos] = s;
    }
}

// ---------------- tf32 tensor-core GEMM + fused s,d epilogue ------------------
#define BM 128
#define BN 64
#define BK 32
#define ASTRIDE 36
#define BSTRIDE 72

__device__ __forceinline__ float cvt_tf32(float x) {
    uint32_t r;
    asm("cvt.rna.tf32.f32 %0, %1;" : "=r"(r) : "f"(x));
    return __uint_as_float(r);
}

__device__ __forceinline__ void mma_tf32(float c[4], const float a[4], const float b[2]) {
    asm volatile(
        "mma.sync.aligned.m16n8k8.row.col.f32.tf32.tf32.f32 "
        "{%0,%1,%2,%3}, {%4,%5,%6,%7}, {%8,%9}, {%0,%1,%2,%3};"
        : "+f"(c[0]), "+f"(c[1]), "+f"(c[2]), "+f"(c[3])
        : "r"(__float_as_uint(a[0])), "r"(__float_as_uint(a[1])),
          "r"(__float_as_uint(a[2])), "r"(__float_as_uint(a[3])),
          "r"(__float_as_uint(b[0])), "r"(__float_as_uint(b[1])));
}

template <int LAYER>
__global__ __launch_bounds__(256) void gemm_tf32_kernel(
    const float* __restrict__ Ain, const float* __restrict__ B,
    const float* __restrict__ a_src, const float* __restrict__ a_dst)
{
    constexpr int N = (LAYER == 1) ? CH1 : CH2;
    constexpr int K = (LAYER == 1) ? IN_CH : CH1;
    const int M = N_NODES;
    __nv_bfloat162* Cb = (LAYER == 1) ? g_h1b : g_h2b;
    float* gs = (LAYER == 1) ? g_s1 : g_s2;
    float* gd = (LAYER == 1) ? g_d1 : g_d2;

    __shared__ float As[BM][ASTRIDE];
    __shared__ float Bs[BK][BSTRIDE];

    int tid = threadIdx.x;
    int brow = blockIdx.y * BM;
    int bcol = blockIdx.x * BN;
    int wid = tid >> 5, lane = tid & 31;
    int wm = wid & 3, wn = wid >> 2;
    int grp = lane >> 2;
    int q = lane & 3;

    int ar = tid >> 3;
    int ac4 = (tid & 7) << 2;
    int ar2 = tid >> 2;
    int ac8 = (tid & 3) << 3;
    int bc4 = (tid & 15) << 2;
    int br0 = tid >> 4;

    float4 ra[4];
    uint4  rab[2];
    float4 rb[2];

    auto load_regs = [&](int k0) {
        if (LAYER == 1) {
            #pragma unroll
            for (int i = 0; i < 4; i++) {
                int gr = brow + ar + i * 32;
                ra[i] = make_float4(0.f, 0.f, 0.f, 0.f);
                if (gr < M) ra[i] = *(const float4*)&Ain[(size_t)gr * K + k0 + ac4];
            }
        } else {
            #pragma unroll
            for (int i = 0; i < 2; i++) {
                int gr = brow + ar2 + i * 64;
                rab[i] = make_uint4(0, 0, 0, 0);
                if (gr < M)
                    rab[i] = *(const uint4*)&g_h1gatb[((size_t)gr * K + k0 + ac8) >> 1];
            }
        }
        #pragma unroll
        for (int i = 0; i < 2; i++) {
            int r = br0 + i * 16;
            rb[i] = *(const float4*)&B[(size_t)(k0 + r) * N + bcol + bc4];
        }
    };
    auto store_smem = [&]() {
        if (LAYER == 1) {
            #pragma unroll
            for (int i = 0; i < 4; i++) {
                int r = ar + i * 32;
                As[r][ac4 + 0] = cvt_tf32(ra[i].x);
                As[r][ac4 + 1] = cvt_tf32(ra[i].y);
                As[r][ac4 + 2] = cvt_tf32(ra[i].z);
                As[r][ac4 + 3] = cvt_tf32(ra[i].w);
            }
        } else {
            #pragma unroll
            for (int i = 0; i < 2; i++) {
                int r = ar2 + i * 64;
                const __nv_bfloat162* p = (const __nv_bfloat162*)&rab[i];
                #pragma unroll
                for (int j = 0; j < 4; j++) {
                    float2 f = __bfloat1622float2(p[j]);
                    As[r][ac8 + j * 2 + 0] = f.x;
                    As[r][ac8 + j * 2 + 1] = f.y;
                }
            }
        }
        #pragma unroll
        for (int i = 0; i < 2; i++) {
            int r = br0 + i * 16;
            Bs[r][bc4 + 0] = cvt_tf32(rb[i].x);
            Bs[r][bc4 + 1] = cvt_tf32(rb[i].y);
            Bs[r][bc4 + 2] = cvt_tf32(rb[i].z);
            Bs[r][bc4 + 3] = cvt_tf32(rb[i].w);
        }
    };

    float c[2][4][4];
    #pragma unroll
    for (int mt = 0; mt < 2; mt++)
        #pragma unroll
        for (int nt = 0; nt < 4; nt++)
            #pragma unroll
            for (int r = 0; r < 4; r++) c[mt][nt][r] = 0.f;

    load_regs(0);
    store_smem();
    __syncthreads();

    for (int k0 = 0; k0 < K; k0 += BK) {
        bool has_next = (k0 + BK) < K;
        if (has_next) load_regs(k0 + BK);

        #pragma unroll
        for (int ks = 0; ks < BK / 8; ks++) {
            int kk = ks * 8;
            float a[2][4], b[4][2];
            #pragma unroll
            for (int mt = 0; mt < 2; mt++) {
                int mb = wm * 32 + mt * 16 + grp;
                a[mt][0] = As[mb][kk + q];
                a[mt][1] = As[mb + 8][kk + q];
                a[mt][2] = As[mb][kk + q + 4];
                a[mt][3] = As[mb + 8][kk + q + 4];
            }
            #pragma unroll
            for (int nt = 0; nt < 4; nt++) {
                int nb = wn * 32 + nt * 8 + grp;
                b[nt][0] = Bs[kk + q][nb];
                b[nt][1] = Bs[kk + q + 4][nb];
            }
            #pragma unroll
            for (int mt = 0; mt < 2; mt++)
                #pragma unroll
                for (int nt = 0; nt < 4; nt++)
                    mma_tf32(c[mt][nt], a[mt], b[nt]);
        }
        __syncthreads();
        if (has_next) {
            store_smem();
            __syncthreads();
        }
    }

    // ---- epilogue 1: pack fp32 -> bf162 store of h ----
    #pragma unroll
    for (int mt = 0; mt < 2; mt++) {
        int rg0 = brow + wm * 32 + mt * 16 + grp;
        #pragma unroll
        for (int nt = 0; nt < 4; nt++) {
            int cg = bcol + wn * 32 + nt * 8 + q * 2;
            if (rg0 < M)
                Cb[((size_t)rg0 * N + cg) >> 1] =
                    __floats2bfloat162_rn(c[mt][nt][0], c[mt][nt][1]);
            if (rg0 + 8 < M)
                Cb[((size_t)(rg0 + 8) * N + cg) >> 1] =
                    __floats2bfloat162_rn(c[mt][nt][2], c[mt][nt][3]);
        }
    }

    // ---- epilogue 2: fused s,d per (row, head) ----
    constexpr int HC = (LAYER == 1) ? HID_CH : OUT_CH;
    float ps[2][2] = {{0.f, 0.f}, {0.f, 0.f}};
    float pd[2][2] = {{0.f, 0.f}, {0.f, 0.f}};
    {
        int hh = (LAYER == 1) ? (bcol / HID_CH) : (bcol / OUT_CH + wn);
        #pragma unroll
        for (int nt = 0; nt < 4; nt++) {
            int ch = (LAYER == 1) ? (wn * 32 + nt * 8 + q * 2) : (nt * 8 + q * 2);
            float a0 = a_src[hh * HC + ch], a1 = a_src[hh * HC + ch + 1];
            float d0 = a_dst[hh * HC + ch], d1 = a_dst[hh * HC + ch + 1];
            #pragma unroll
            for (int mt = 0; mt < 2; mt++) {
                ps[mt][0] += c[mt][nt][0] * a0 + c[mt][nt][1] * a1;
                pd[mt][0] += c[mt][nt][0] * d0 + c[mt][nt][1] * d1;
                ps[mt][1] += c[mt][nt][2] * a0 + c[mt][nt][3] * a1;
                pd[mt][1] += c[mt][nt][2] * d0 + c[mt][nt][3] * d1;
            }
        }
        #pragma unroll
        for (int mt = 0; mt < 2; mt++)
            #pragma unroll
            for (int hf = 0; hf < 2; hf++) {
                ps[mt][hf] += __shfl_down_sync(0xffffffff, ps[mt][hf], 2);
                ps[mt][hf] += __shfl_down_sync(0xffffffff, ps[mt][hf], 1);
                pd[mt][hf] += __shfl_down_sync(0xffffffff, pd[mt][hf], 2);
                pd[mt][hf] += __shfl_down_sync(0xffffffff, pd[mt][hf], 1);
            }

        if (LAYER == 2) {
            if (q == 0) {
                #pragma unroll
                for (int mt = 0; mt < 2; mt++)
                    #pragma unroll
                    for (int hf = 0; hf < 2; hf++) {
                        int grow = brow + wm * 32 + mt * 16 + grp + hf * 8;
                        if (grow < M) {
                            gs[grow * HEADS + hh] = ps[mt][hf];
                            gd[grow * HEADS + hh] = pd[mt][hf];
                        }
                    }
            }
        } else {
            float* red = &As[0][0];
            if (q == 0) {
                #pragma unroll
                for (int mt = 0; mt < 2; mt++)
                    #pragma unroll
                    for (int hf = 0; hf < 2; hf++) {
                        int row = wm * 32 + mt * 16 + grp + hf * 8;
                        red[wn * 256 + row * 2 + 0] = ps[mt][hf];
                        red[wn * 256 + row * 2 + 1] = pd[mt][hf];
                    }
            }
            __syncthreads();
            if (tid < 128) {
                int grow = brow + tid;
                if (grow < M) {
                    float sv = red[tid * 2]     + red[256 + tid * 2];
                    float dv = red[tid * 2 + 1] + red[256 + tid * 2 + 1];
                    gs[grow * HEADS + hh] = sv;
                    gd[grow * HEADS + hh] = dv;
                }
            }
        }
    }
}

// ---------------- warp-per-node GAT softmax-aggregate (vectorized) ------------
template <int LAYER>
__global__ __launch_bounds__(256) void agg_kernel(const float* __restrict__ bias,
                                                  const int* __restrict__ batch,
                                                  const float* __restrict__ Wout)
{
    constexpr int CH = (LAYER == 1) ? CH1 : CH2;
    constexpr int PAIRS = CH / 2;             // 128 / 64
    constexpr int PPL = PAIRS / 32;           // 4 / 2 pairs per lane

    int n = blockIdx.x * (blockDim.x >> 5) + (threadIdx.x >> 5);
    if (n >= N_NODES) return;
    int lane = threadIdx.x & 31;
    int hh = lane >> 3;
    int p0 = lane * PPL;

    const __nv_bfloat162* hb = (LAYER == 1) ? g_h1b : g_h2b;
    const float* s = (LAYER == 1) ? g_s1 : g_s2;
    const float* d = (LAYER == 1) ? g_d1 : g_d2;

    float4 dn4 = *(const float4*)&d[n * 4];
    float4 ss4 = *(const float4*)&s[n * 4];

    float wself4[HEADS];
    wself4[0] = __expf(lrelu(ss4.x + dn4.x));
    wself4[1] = __expf(lrelu(ss4.y + dn4.y));
    wself4[2] = __expf(lrelu(ss4.z + dn4.z));
    wself4[3] = __expf(lrelu(ss4.w + dn4.w));
    float wself = wself4[hh];
    float denom = wself;

    float acc[PPL][2];
    {
        __nv_bfloat162 hv[PPL];
        if (LAYER == 1) *(uint4*)hv = *(const uint4*)&hb[(size_t)n * PAIRS + p0];
        else            *(uint2*)hv = *(const uint2*)&hb[(size_t)n * PAIRS + p0];
        #pragma unroll
        for (int i = 0; i < PPL; i++) {
            float2 f = __bfloat1622float2(hv[i]);
            acc[i][0] = wself * f.x;
            acc[i][1] = wself * f.y;
        }
    }

    int beg = g_indptr[n], end = g_indptr[n + 1];
    for (int base = beg; base < end; base += 32) {
        int m = min(32, end - base);
        int srcl = 0;
        float4 wl = make_float4(0.f, 0.f, 0.f, 0.f);
        if (lane < m) {
            srcl = g_esrc[base + lane];
            float4 s4 = *(const float4*)&s[srcl * 4];
            wl.x = __expf(lrelu(s4.x + dn4.x));
            wl.y = __expf(lrelu(s4.y + dn4.y));
            wl.z = __expf(lrelu(s4.z + dn4.z));
            wl.w = __expf(lrelu(s4.w + dn4.w));
        }
        #pragma unroll 4
        for (int j = 0; j < m; j++) {
            int src = __shfl_sync(0xffffffffu, srcl, j);
            float w0 = __shfl_sync(0xffffffffu, wl.x, j);
            float w1 = __shfl_sync(0xffffffffu, wl.y, j);
            float w2 = __shfl_sync(0xffffffffu, wl.z, j);
            float w3 = __shfl_sync(0xffffffffu, wl.w, j);
            float w = (hh == 0) ? w0 : (hh == 1) ? w1 : (hh == 2) ? w2 : w3;
            __nv_bfloat162 hv[PPL];
            if (LAYER == 1) *(uint4*)hv = *(const uint4*)&hb[(size_t)src * PAIRS + p0];
            else            *(uint2*)hv = *(const uint2*)&hb[(size_t)src * PAIRS + p0];
            #pragma unroll
            for (int i = 0; i < PPL; i++) {
                float2 f = __bfloat1622float2(hv[i]);
                acc[i][0] += w * f.x;
                acc[i][1] += w * f.y;
            }
            denom += w;
        }
    }

    float inv = 1.f / (denom + 1e-16f);

    if (LAYER == 1) {
        __nv_bfloat162 ov[PPL];
        #pragma unroll
        for (int i = 0; i < PPL; i++) {
            int p = p0 + i;
            float2 bi = *(const float2*)&bias[2 * p];
            float v0 = fmaxf(acc[i][0] * inv + bi.x, 0.f);
            float v1 = fmaxf(acc[i][1] * inv + bi.y, 0.f);
            ov[i] = __floats2bfloat162_rn(v0, v1);
        }
        *(uint4*)&g_h1gatb[(size_t)n * PAIRS + p0] = *(uint4*)ov;
    } else {
        float l0 = 0.f, l1 = 0.f;
        #pragma unroll
        for (int i = 0; i < PPL; i++) {
            int p = p0 + i;
            float2 bi = *(const float2*)&bias[2 * p];
            float v0 = fmaxf(acc[i][0] * inv + bi.x, 0.f);
            float v1 = fmaxf(acc[i][1] * inv + bi.y, 0.f);
            float4 w = *(const float4*)&Wout[4 * p];
            l0 += v0 * w.x + v1 * w.z;
            l1 += v0 * w.y + v1 * w.w;
        }
        #pragma unroll
        for (int off = 16; off > 0; off >>= 1) {
            l0 += __shfl_down_sync(0xffffffffu, l0, off);
            l1 += __shfl_down_sync(0xffffffffu, l1, off);
        }
        if (lane == 0) {
            int gb = batch[n];
            atomicAdd(&g_lsum[gb * 2 + 0], l0);
            atomicAdd(&g_lsum[gb * 2 + 1], l1);
            atomicAdd(&g_counts[gb], 1);
        }
    }
}

// ---------------- final logits + softmax (+ scratch re-zero) ------------------
__global__ void final_kernel(const float* __restrict__ bout,
                             float* __restrict__ out)
{
    int g = threadIdx.x;
    if (g >= N_GRAPHS) return;
    float cnt = fmaxf((float)g_counts[g], 1.0f);
    float l0 = g_lsum[g * 2 + 0] / cnt + bout[0];
    float l1 = g_lsum[g * 2 + 1] / cnt + bout[1];
    float mx = fmaxf(l0, l1);
    float e0 = expf(l0 - mx), e1 = expf(l1 - mx);
    float inv = 1.f / (e0 + e1);
    out[g * 2 + 0] = e0 * inv;
    out[g * 2 + 1] = e1 * inv;
    g_lsum[g * 2 + 0] = 0.f;
    g_lsum[g * 2 + 1] = 0.f;
    g_counts[g] = 0;
}

// ---------------- launch (CSR build forked onto a side stream) ----------------
extern "C" void kernel_launch(void* const* d_in, const int* in_sizes, int n_in,
                              void* d_out, int out_size) {
    const float* x      = (const float*)d_in[0];
    const int*   ei     = (const int*)d_in[1];
    const int*   batch  = (const int*)d_in[2];
    const float* W1     = (const float*)d_in[3];
    const float* a_src1 = (const float*)d_in[4];
    const float* a_dst1 = (const float*)d_in[5];
    const float* b1     = (const float*)d_in[6];
    const float* W2     = (const float*)d_in[7];
    const float* a_src2 = (const float*)d_in[8];
    const float* a_dst2 = (const float*)d_in[9];
    const float* b2     = (const float*)d_in[10];
    const float* Wout   = (const float*)d_in[11];
    const float* bout   = (const float*)d_in[12];
    float* out = (float*)d_out;

    // fork: CSR build (depends only on ei) runs concurrently with GEMM1
    cudaStream_t s2;
    cudaStreamCreateWithFlags(&s2, cudaStreamNonBlocking);
    cudaEvent_t eFork, eJoin;
    cudaEventCreateWithFlags(&eFork, cudaEventDisableTiming);
    cudaEventCreateWithFlags(&eJoin, cudaEventDisableTiming);

    cudaEventRecord(eFork, (cudaStream_t)0);
    cudaStreamWaitEvent(s2, eFork, 0);

    count_kernel<<<(N_EDGES + 255) / 256, 256, 0, s2>>>(ei);
    scan1_kernel<<<NB, SCAN_B, 0, s2>>>();
    scan23_kernel<<<(N_NODES + 255) / 256, 256, 0, s2>>>();
    scatter_kernel<<<(N_EDGES + 255) / 256, 256, 0, s2>>>(ei);
    cudaEventRecord(eJoin, s2);

    {
        dim3 grid(CH1 / BN, (N_NODES + BM - 1) / BM);
        gemm_tf32_kernel<1><<<grid, 256>>>(x, W1, a_src1, a_dst1);
    }

    // join: agg1 needs both CSR and GEMM1
    cudaStreamWaitEvent((cudaStream_t)0, eJoin, 0);

    agg_kernel<1><<<(N_NODES * 32 + 255) / 256, 256>>>(b1, batch, Wout);

    {
        dim3 grid(CH2 / BN, (N_NODES + BM - 1) / BM);
        gemm_tf32_kernel<2><<<grid, 256>>>(nullptr, W2, a_src2, a_dst2);
    }
    agg_kernel<2><<<(N_NODES * 32 + 255) / 256, 256>>>(b2, batch, Wout);

    final_kernel<<<1, 64>>>(bout, out);
}

// round 15
// speedup vs baseline: 1.1079x; 1.0834x over previous
#include <cuda_runtime.h>
#include <cuda_bf16.h>
#include <math.h>
#include <stdint.h>

#define N_NODES 50000
#define N_EDGES 800000
#define N_GRAPHS 64
#define HEADS 4
#define IN_CH 128
#define HID_CH 64
#define OUT_CH 32
#define CH1 (HEADS*HID_CH)   // 256
#define CH2 (HEADS*OUT_CH)   // 128

#define SCAN_B 1024
#define NB ((N_NODES + SCAN_B - 1) / SCAN_B)   // 49

// ---------------- scratch (device globals) ----------------------------------
// INVARIANT: g_cnt, g_lsum, g_counts are all-zero at kernel_launch entry.
__device__ __nv_bfloat162 g_h1b[N_NODES * CH1 / 2];
__device__ __nv_bfloat162 g_h1gatb[N_NODES * CH1 / 2];
__device__ __nv_bfloat162 g_h2b[N_NODES * CH2 / 2];
__device__ float g_s1[N_NODES * HEADS], g_d1[N_NODES * HEADS];
__device__ float g_s2[N_NODES * HEADS], g_d2[N_NODES * HEADS];
__device__ int   g_cnt[N_NODES];
__device__ int   g_incl[N_NODES];
__device__ int   g_indptr[N_NODES + 1];
__device__ int   g_esrc[N_EDGES];
__device__ int   g_edst[N_EDGES];
__device__ float g_w[N_EDGES * 4];           // per-edge per-head weights
__device__ int   g_blocksums[NB];
__device__ float g_lsum[N_GRAPHS * 2];
__device__ int   g_counts[N_GRAPHS];

__device__ __forceinline__ float lrelu(float x) {
    return x > 0.f ? x : 0.2f * x;
}

// ---------------- CSR build --------------------------------------------------
__global__ void count_kernel(const int* __restrict__ ei) {
    int e = blockIdx.x * blockDim.x + threadIdx.x;
    if (e < N_EDGES) atomicAdd(&g_cnt[ei[N_EDGES + e]], 1);
}

__global__ void scan1_kernel() {
    __shared__ int sh[SCAN_B];
    int i = blockIdx.x * SCAN_B + threadIdx.x;
    int v = (i < N_NODES) ? g_cnt[i] : 0;
    sh[threadIdx.x] = v;
    __syncthreads();
    #pragma unroll
    for (int off = 1; off < SCAN_B; off <<= 1) {
        int t = (threadIdx.x >= off) ? sh[threadIdx.x - off] : 0;
        __syncthreads();
        sh[threadIdx.x] += t;
        __syncthreads();
    }
    if (i < N_NODES) g_incl[i] = sh[threadIdx.x];
    if (threadIdx.x == SCAN_B - 1) g_blocksums[blockIdx.x] = sh[SCAN_B - 1];
}

// fused scan2+scan3 (g_blocksums left unmodified)
__global__ void scan23_kernel() {
    __shared__ int incl[64];
    __shared__ int excl[64];
    int t = threadIdx.x;
    int own = 0;
    if (t < 64) {
        own = (t < NB) ? g_blocksums[t] : 0;
        incl[t] = own;
    }
    __syncthreads();
    #pragma unroll
    for (int off = 1; off < 64; off <<= 1) {
        int u = (t >= off && t < 64) ? incl[t - off] : 0;
        __syncthreads();
        if (t < 64) incl[t] += u;
        __syncthreads();
    }
    if (t < 64) excl[t] = incl[t] - own;
    __syncthreads();
    int i = blockIdx.x * blockDim.x + t;
    if (i < N_NODES) g_indptr[i + 1] = g_incl[i] + excl[i / SCAN_B];
    if (i == 0) g_indptr[0] = 0;
}

// scatter: atomicSub restores g_cnt to 0; also records dst per CSR slot
__global__ void scatter_kernel(const int* __restrict__ ei) {
    int e = blockIdx.x * blockDim.x + threadIdx.x;
    if (e < N_EDGES) {
        int s = ei[e];
        int d = ei[N_EDGES + e];
        int pos = g_indptr[d] + atomicSub(&g_cnt[d], 1) - 1;
        g_esrc[pos] = s;
        g_edst[pos] = d;
    }
}

// ---------------- edge-parallel attention weights -----------------------------
template <int LAYER>
__global__ void weight_kernel() {
    int e = blockIdx.x * blockDim.x + threadIdx.x;
    if (e >= N_EDGES) return;
    const float* s = (LAYER == 1) ? g_s1 : g_s2;
    const float* d = (LAYER == 1) ? g_d1 : g_d2;
    int src = g_esrc[e];
    int dst = g_edst[e];
    float4 s4 = *(const float4*)&s[src * 4];
    float4 d4 = *(const float4*)&d[dst * 4];
    float4 w4;
    w4.x = __expf(lrelu(s4.x + d4.x));
    w4.y = __expf(lrelu(s4.y + d4.y));
    w4.z = __expf(lrelu(s4.z + d4.z));
    w4.w = __expf(lrelu(s4.w + d4.w));
    *(float4*)&g_w[e * 4] = w4;
}

// ---------------- tf32 tensor-core GEMM + fused s,d epilogue ------------------
#define BM 128
#define BN 64
#define BK 32
#define ASTRIDE 36
#define BSTRIDE 72

__device__ __forceinline__ float cvt_tf32(float x) {
    uint32_t r;
    asm("cvt.rna.tf32.f32 %0, %1;" : "=r"(r) : "f"(x));
    return __uint_as_float(r);
}

__device__ __forceinline__ void mma_tf32(float c[4], const float a[4], const float b[2]) {
    asm volatile(
        "mma.sync.aligned.m16n8k8.row.col.f32.tf32.tf32.f32 "
        "{%0,%1,%2,%3}, {%4,%5,%6,%7}, {%8,%9}, {%0,%1,%2,%3};"
        : "+f"(c[0]), "+f"(c[1]), "+f"(c[2]), "+f"(c[3])
        : "r"(__float_as_uint(a[0])), "r"(__float_as_uint(a[1])),
          "r"(__float_as_uint(a[2])), "r"(__float_as_uint(a[3])),
          "r"(__float_as_uint(b[0])), "r"(__float_as_uint(b[1])));
}

template <int LAYER>
__global__ __launch_bounds__(256) void gemm_tf32_kernel(
    const float* __restrict__ Ain, const float* __restrict__ B,
    const float* __restrict__ a_src, const float* __restrict__ a_dst)
{
    constexpr int N = (LAYER == 1) ? CH1 : CH2;
    constexpr int K = (LAYER == 1) ? IN_CH : CH1;
    const int M = N_NODES;
    __nv_bfloat162* Cb = (LAYER == 1) ? g_h1b : g_h2b;
    float* gs = (LAYER == 1) ? g_s1 : g_s2;
    float* gd = (LAYER == 1) ? g_d1 : g_d2;

    __shared__ float As[BM][ASTRIDE];
    __shared__ float Bs[BK][BSTRIDE];

    int tid = threadIdx.x;
    int brow = blockIdx.y * BM;
    int bcol = blockIdx.x * BN;
    int wid = tid >> 5, lane = tid & 31;
    int wm = wid & 3, wn = wid >> 2;
    int grp = lane >> 2;
    int q = lane & 3;

    int ar = tid >> 3;
    int ac4 = (tid & 7) << 2;
    int ar2 = tid >> 2;
    int ac8 = (tid & 3) << 3;
    int bc4 = (tid & 15) << 2;
    int br0 = tid >> 4;

    float4 ra[4];
    uint4  rab[2];
    float4 rb[2];

    auto load_regs = [&](int k0) {
        if (LAYER == 1) {
            #pragma unroll
            for (int i = 0; i < 4; i++) {
                int gr = brow + ar + i * 32;
                ra[i] = make_float4(0.f, 0.f, 0.f, 0.f);
                if (gr < M) ra[i] = *(const float4*)&Ain[(size_t)gr * K + k0 + ac4];
            }
        } else {
            #pragma unroll
            for (int i = 0; i < 2; i++) {
                int gr = brow + ar2 + i * 64;
                rab[i] = make_uint4(0, 0, 0, 0);
                if (gr < M)
                    rab[i] = *(const uint4*)&g_h1gatb[((size_t)gr * K + k0 + ac8) >> 1];
            }
        }
        #pragma unroll
        for (int i = 0; i < 2; i++) {
            int r = br0 + i * 16;
            rb[i] = *(const float4*)&B[(size_t)(k0 + r) * N + bcol + bc4];
        }
    };
    auto store_smem = [&]() {
        if (LAYER == 1) {
            #pragma unroll
            for (int i = 0; i < 4; i++) {
                int r = ar + i * 32;
                As[r][ac4 + 0] = cvt_tf32(ra[i].x);
                As[r][ac4 + 1] = cvt_tf32(ra[i].y);
                As[r][ac4 + 2] = cvt_tf32(ra[i].z);
                As[r][ac4 + 3] = cvt_tf32(ra[i].w);
            }
        } else {
            #pragma unroll
            for (int i = 0; i < 2; i++) {
                int r = ar2 + i * 64;
                const __nv_bfloat162* p = (const __nv_bfloat162*)&rab[i];
                #pragma unroll
                for (int j = 0; j < 4; j++) {
                    float2 f = __bfloat1622float2(p[j]);
                    As[r][ac8 + j * 2 + 0] = f.x;
                    As[r][ac8 + j * 2 + 1] = f.y;
                }
            }
        }
        #pragma unroll
        for (int i = 0; i < 2; i++) {
            int r = br0 + i * 16;
            Bs[r][bc4 + 0] = cvt_tf32(rb[i].x);
            Bs[r][bc4 + 1] = cvt_tf32(rb[i].y);
            Bs[r][bc4 + 2] = cvt_tf32(rb[i].z);
            Bs[r][bc4 + 3] = cvt_tf32(rb[i].w);
        }
    };

    float c[2][4][4];
    #pragma unroll
    for (int mt = 0; mt < 2; mt++)
        #pragma unroll
        for (int nt = 0; nt < 4; nt++)
            #pragma unroll
            for (int r = 0; r < 4; r++) c[mt][nt][r] = 0.f;

    load_regs(0);
    store_smem();
    __syncthreads();

    for (int k0 = 0; k0 < K; k0 += BK) {
        bool has_next = (k0 + BK) < K;
        if (has_next) load_regs(k0 + BK);

        #pragma unroll
        for (int ks = 0; ks < BK / 8; ks++) {
            int kk = ks * 8;
            float a[2][4], b[4][2];
            #pragma unroll
            for (int mt = 0; mt < 2; mt++) {
                int mb = wm * 32 + mt * 16 + grp;
                a[mt][0] = As[mb][kk + q];
                a[mt][1] = As[mb + 8][kk + q];
                a[mt][2] = As[mb][kk + q + 4];
                a[mt][3] = As[mb + 8][kk + q + 4];
            }
            #pragma unroll
            for (int nt = 0; nt < 4; nt++) {
                int nb = wn * 32 + nt * 8 + grp;
                b[nt][0] = Bs[kk + q][nb];
                b[nt][1] = Bs[kk + q + 4][nb];
            }
            #pragma unroll
            for (int mt = 0; mt < 2; mt++)
                #pragma unroll
                for (int nt = 0; nt < 4; nt++)
                    mma_tf32(c[mt][nt], a[mt], b[nt]);
        }
        __syncthreads();
        if (has_next) {
            store_smem();
            __syncthreads();
        }
    }

    // ---- epilogue 1: pack fp32 -> bf162 store of h ----
    #pragma unroll
    for (int mt = 0; mt < 2; mt++) {
        int rg0 = brow + wm * 32 + mt * 16 + grp;
        #pragma unroll
        for (int nt = 0; nt < 4; nt++) {
            int cg = bcol + wn * 32 + nt * 8 + q * 2;
            if (rg0 < M)
                Cb[((size_t)rg0 * N + cg) >> 1] =
                    __floats2bfloat162_rn(c[mt][nt][0], c[mt][nt][1]);
            if (rg0 + 8 < M)
                Cb[((size_t)(rg0 + 8) * N + cg) >> 1] =
                    __floats2bfloat162_rn(c[mt][nt][2], c[mt][nt][3]);
        }
    }

    // ---- epilogue 2: fused s,d per (row, head) ----
    constexpr int HC = (LAYER == 1) ? HID_CH : OUT_CH;
    float ps[2][2] = {{0.f, 0.f}, {0.f, 0.f}};
    float pd[2][2] = {{0.f, 0.f}, {0.f, 0.f}};
    {
        int hh = (LAYER == 1) ? (bcol / HID_CH) : (bcol / OUT_CH + wn);
        #pragma unroll
        for (int nt = 0; nt < 4; nt++) {
            int ch = (LAYER == 1) ? (wn * 32 + nt * 8 + q * 2) : (nt * 8 + q * 2);
            float a0 = a_src[hh * HC + ch], a1 = a_src[hh * HC + ch + 1];
            float d0 = a_dst[hh * HC + ch], d1 = a_dst[hh * HC + ch + 1];
            #pragma unroll
            for (int mt = 0; mt < 2; mt++) {
                ps[mt][0] += c[mt][nt][0] * a0 + c[mt][nt][1] * a1;
                pd[mt][0] += c[mt][nt][0] * d0 + c[mt][nt][1] * d1;
                ps[mt][1] += c[mt][nt][2] * a0 + c[mt][nt][3] * a1;
                pd[mt][1] += c[mt][nt][2] * d0 + c[mt][nt][3] * d1;
            }
        }
        #pragma unroll
        for (int mt = 0; mt < 2; mt++)
            #pragma unroll
            for (int hf = 0; hf < 2; hf++) {
                ps[mt][hf] += __shfl_down_sync(0xffffffff, ps[mt][hf], 2);
                ps[mt][hf] += __shfl_down_sync(0xffffffff, ps[mt][hf], 1);
                pd[mt][hf] += __shfl_down_sync(0xffffffff, pd[mt][hf], 2);
                pd[mt][hf] += __shfl_down_sync(0xffffffff, pd[mt][hf], 1);
            }

        if (LAYER == 2) {
            if (q == 0) {
                #pragma unroll
                for (int mt = 0; mt < 2; mt++)
                    #pragma unroll
                    for (int hf = 0; hf < 2; hf++) {
                        int grow = brow + wm * 32 + mt * 16 + grp + hf * 8;
                        if (grow < M) {
                            gs[grow * HEADS + hh] = ps[mt][hf];
                            gd[grow * HEADS + hh] = pd[mt][hf];
                        }
                    }
            }
        } else {
            float* red = &As[0][0];
            if (q == 0) {
                #pragma unroll
                for (int mt = 0; mt < 2; mt++)
                    #pragma unroll
                    for (int hf = 0; hf < 2; hf++) {
                        int row = wm * 32 + mt * 16 + grp + hf * 8;
                        red[wn * 256 + row * 2 + 0] = ps[mt][hf];
                        red[wn * 256 + row * 2 + 1] = pd[mt][hf];
                    }
            }
            __syncthreads();
            if (tid < 128) {
                int grow = brow + tid;
                if (grow < M) {
                    float sv = red[tid * 2]     + red[256 + tid * 2];
                    float dv = red[tid * 2 + 1] + red[256 + tid * 2 + 1];
                    gs[grow * HEADS + hh] = sv;
                    gd[grow * HEADS + hh] = dv;
                }
            }
        }
    }
}

// ---------------- warp-per-node GAT aggregate (precomputed weights) -----------
// No shfl, no exp in the hot loop: per edge, uniform esrc load + per-head w
// load + vectorized h row gather; all loads independent across edges.
template <int LAYER>
__global__ __launch_bounds__(256) void agg_kernel(const float* __restrict__ bias,
                                                  const int* __restrict__ batch,
                                                  const float* __restrict__ Wout)
{
    constexpr int CH = (LAYER == 1) ? CH1 : CH2;
    constexpr int PAIRS = CH / 2;             // 128 / 64
    constexpr int PPL = PAIRS / 32;           // 4 / 2 pairs per lane

    int n = blockIdx.x * (blockDim.x >> 5) + (threadIdx.x >> 5);
    if (n >= N_NODES) return;
    int lane = threadIdx.x & 31;
    int hh = lane >> 3;
    int p0 = lane * PPL;

    const __nv_bfloat162* hb = (LAYER == 1) ? g_h1b : g_h2b;
    const float* s = (LAYER == 1) ? g_s1 : g_s2;
    const float* d = (LAYER == 1) ? g_d1 : g_d2;

    float4 dn4 = *(const float4*)&d[n * 4];
    float4 ss4 = *(const float4*)&s[n * 4];
    const float* dnp = (const float*)&dn4;
    const float* ssp = (const float*)&ss4;

    float wself = __expf(lrelu(ssp[hh] + dnp[hh]));
    float denom = wself;

    float acc[PPL][2];
    {
        __nv_bfloat162 hv[PPL];
        if (LAYER == 1) *(uint4*)hv = *(const uint4*)&hb[(size_t)n * PAIRS + p0];
        else            *(uint2*)hv = *(const uint2*)&hb[(size_t)n * PAIRS + p0];
        #pragma unroll
        for (int i = 0; i < PPL; i++) {
            float2 f = __bfloat1622float2(hv[i]);
            acc[i][0] = wself * f.x;
            acc[i][1] = wself * f.y;
        }
    }

    int beg = g_indptr[n], end = g_indptr[n + 1];
    #pragma unroll 4
    for (int e = beg; e < end; e++) {
        int src = __ldg(&g_esrc[e]);            // uniform broadcast
        float w = __ldg(&g_w[4 * e + hh]);      // 1 sector per warp
        __nv_bfloat162 hv[PPL];
        if (LAYER == 1) *(uint4*)hv = *(const uint4*)&hb[(size_t)src * PAIRS + p0];
        else            *(uint2*)hv = *(const uint2*)&hb[(size_t)src * PAIRS + p0];
        #pragma unroll
        for (int i = 0; i < PPL; i++) {
            float2 f = __bfloat1622float2(hv[i]);
            acc[i][0] += w * f.x;
            acc[i][1] += w * f.y;
        }
        denom += w;
    }

    float inv = 1.f / (denom + 1e-16f);

    if (LAYER == 1) {
        __nv_bfloat162 ov[PPL];
        #pragma unroll
        for (int i = 0; i < PPL; i++) {
            int p = p0 + i;
            float2 bi = *(const float2*)&bias[2 * p];
            float v0 = fmaxf(acc[i][0] * inv + bi.x, 0.f);
            float v1 = fmaxf(acc[i][1] * inv + bi.y, 0.f);
            ov[i] = __floats2bfloat162_rn(v0, v1);
        }
        *(uint4*)&g_h1gatb[(size_t)n * PAIRS + p0] = *(uint4*)ov;
    } else {
        float l0 = 0.f, l1 = 0.f;
        #pragma unroll
        for (int i = 0; i < PPL; i++) {
            int p = p0 + i;
            float2 bi = *(const float2*)&bias[2 * p];
            float v0 = fmaxf(acc[i][0] * inv + bi.x, 0.f);
            float v1 = fmaxf(acc[i][1] * inv + bi.y, 0.f);
            float4 w = *(const float4*)&Wout[4 * p];
            l0 += v0 * w.x + v1 * w.z;
            l1 += v0 * w.y + v1 * w.w;
        }
        #pragma unroll
        for (int off = 16; off > 0; off >>= 1) {
            l0 += __shfl_down_sync(0xffffffffu, l0, off);
            l1 += __shfl_down_sync(0xffffffffu, l1, off);
        }
        if (lane == 0) {
            int gb = batch[n];
            atomicAdd(&g_lsum[gb * 2 + 0], l0);
            atomicAdd(&g_lsum[gb * 2 + 1], l1);
            atomicAdd(&g_counts[gb], 1);
        }
    }
}

// ---------------- final logits + softmax (+ scratch re-zero) ------------------
__global__ void final_kernel(const float* __restrict__ bout,
                             float* __restrict__ out)
{
    int g = threadIdx.x;
    if (g >= N_GRAPHS) return;
    float cnt = fmaxf((float)g_counts[g], 1.0f);
    float l0 = g_lsum[g * 2 + 0] / cnt + bout[0];
    float l1 = g_lsum[g * 2 + 1] / cnt + bout[1];
    float mx = fmaxf(l0, l1);
    float e0 = expf(l0 - mx), e1 = expf(l1 - mx);
    float inv = 1.f / (e0 + e1);
    out[g * 2 + 0] = e0 * inv;
    out[g * 2 + 1] = e1 * inv;
    g_lsum[g * 2 + 0] = 0.f;
    g_lsum[g * 2 + 1] = 0.f;
    g_counts[g] = 0;
}

// ---------------- launch (CSR build forked onto a side stream) ----------------
extern "C" void kernel_launch(void* const* d_in, const int* in_sizes, int n_in,
                              void* d_out, int out_size) {
    const float* x      = (const float*)d_in[0];
    const int*   ei     = (const int*)d_in[1];
    const int*   batch  = (const int*)d_in[2];
    const float* W1     = (const float*)d_in[3];
    const float* a_src1 = (const float*)d_in[4];
    const float* a_dst1 = (const float*)d_in[5];
    const float* b1     = (const float*)d_in[6];
    const float* W2     = (const float*)d_in[7];
    const float* a_src2 = (const float*)d_in[8];
    const float* a_dst2 = (const float*)d_in[9];
    const float* b2     = (const float*)d_in[10];
    const float* Wout   = (const float*)d_in[11];
    const float* bout   = (const float*)d_in[12];
    float* out = (float*)d_out;

    cudaStream_t s2;
    cudaStreamCreateWithFlags(&s2, cudaStreamNonBlocking);
    cudaEvent_t eFork, eJoin;
    cudaEventCreateWithFlags(&eFork, cudaEventDisableTiming);
    cudaEventCreateWithFlags(&eJoin, cudaEventDisableTiming);

    cudaEventRecord(eFork, (cudaStream_t)0);
    cudaStreamWaitEvent(s2, eFork, 0);

    count_kernel<<<(N_EDGES + 255) / 256, 256, 0, s2>>>(ei);
    scan1_kernel<<<NB, SCAN_B, 0, s2>>>();
    scan23_kernel<<<(N_NODES + 255) / 256, 256, 0, s2>>>();
    scatter_kernel<<<(N_EDGES + 255) / 256, 256, 0, s2>>>(ei);
    cudaEventRecord(eJoin, s2);

    {
        dim3 grid(CH1 / BN, (N_NODES + BM - 1) / BM);
        gemm_tf32_kernel<1><<<grid, 256>>>(x, W1, a_src1, a_dst1);
    }

    cudaStreamWaitEvent((cudaStream_t)0, eJoin, 0);

    weight_kernel<1><<<(N_EDGES + 255) / 256, 256>>>();
    agg_kernel<1><<<(N_NODES * 32 + 255) / 256, 256>>>(b1, batch, Wout);

    {
        dim3 grid(CH2 / BN, (N_NODES + BM - 1) / BM);
        gemm_tf32_kernel<2><<<grid, 256>>>(nullptr, W2, a_src2, a_dst2);
    }
    weight_kernel<2><<<(N_EDGES + 255) / 256, 256>>>();
    agg_kernel<2><<<(N_NODES * 32 + 255) / 256, 256>>>(b2, batch, Wout);

    final_kernel<<<1, 64>>>(bout, out);
}